// round 15
// baseline (speedup 1.0000x reference)
#include <cuda_runtime.h>
#include <cuda_bf16.h>
#include <cuda_fp16.h>
#include <math.h>
#include <stdint.h>

#define B_   16
#define NQ   64
#define NKV  4096
#define CQ   768
#define CKV  1024
#define H_   12
#define D_   64
#define SPLIT 4

// ---------------- scratch (device globals; allocation-free) ----------------
__device__ __half g_qa  [(size_t)B_ * NQ * CQ];
__device__ __half g_qh  [(size_t)B_ * NQ * CQ];
__device__ __half g_xh  [(size_t)B_ * NQ * CQ];
__device__ __half g_kh  [(size_t)B_ * NKV * CQ];
__device__ __half g_vh  [(size_t)B_ * NKV * CQ];
__device__ __half g_kva [(size_t)B_ * NKV * CKV];
__device__ __half g_wkvt[(size_t)2 * CQ * CKV];
__device__ __half g_wqth[(size_t)CQ * CQ];
__device__ __half g_wqtl[(size_t)CQ * CQ];
__device__ __half g_woth[(size_t)CQ * CQ];
__device__ __half g_wotl[(size_t)CQ * CQ];
__device__ float g_accP[(size_t)B_ * H_ * SPLIT * NQ * D_];
__device__ float g_mP[(size_t)B_ * H_ * SPLIT * NQ];
__device__ float g_lP[(size_t)B_ * H_ * SPLIT * NQ];
__device__ unsigned int g_cnt[B_ * H_];   // monotonic arrival counters

// ---------------- helpers ----------------
__device__ __forceinline__ uint32_t smem_u32(const void* p) {
    uint32_t a;
    asm("{ .reg .u64 t; cvta.to.shared.u64 t, %1; cvt.u32.u64 %0, t; }"
        : "=r"(a) : "l"(p));
    return a;
}
__device__ __forceinline__ void cp16(uint32_t s, const void* g) {
    asm volatile("cp.async.cg.shared.global [%0], [%1], 16;\n"
                 :: "r"(s), "l"(__cvta_generic_to_global(g)) : "memory");
}
#define CP_COMMIT() asm volatile("cp.async.commit_group;\n" ::: "memory")
#define CP_WAIT(n)  asm volatile("cp.async.wait_group %0;\n" :: "n"(n) : "memory")

__device__ __forceinline__ void ldsm_x4(uint32_t addr, uint32_t& r0, uint32_t& r1,
                                        uint32_t& r2, uint32_t& r3) {
    asm volatile("ldmatrix.sync.aligned.m8n8.x4.shared.b16 {%0,%1,%2,%3}, [%4];"
                 : "=r"(r0), "=r"(r1), "=r"(r2), "=r"(r3) : "r"(addr));
}
__device__ __forceinline__ void ldsm_x4_t(uint32_t addr, uint32_t& r0, uint32_t& r1,
                                          uint32_t& r2, uint32_t& r3) {
    asm volatile("ldmatrix.sync.aligned.m8n8.x4.trans.shared.b16 {%0,%1,%2,%3}, [%4];"
                 : "=r"(r0), "=r"(r1), "=r"(r2), "=r"(r3) : "r"(addr));
}
__device__ __forceinline__ void mma_f16(float* d, uint32_t a0, uint32_t a1,
                                        uint32_t a2, uint32_t a3,
                                        uint32_t b0, uint32_t b1) {
    asm volatile(
        "mma.sync.aligned.m16n8k16.row.col.f32.f16.f16.f32 "
        "{%0,%1,%2,%3}, {%4,%5,%6,%7}, {%8,%9}, {%0,%1,%2,%3};"
        : "+f"(d[0]), "+f"(d[1]), "+f"(d[2]), "+f"(d[3])
        : "r"(a0), "r"(a1), "r"(a2), "r"(a3), "r"(b0), "r"(b1));
}
__device__ __forceinline__ uint32_t pack_h2(float a, float b) {
    __half2 h = __floats2half2_rn(a, b);
    return *(uint32_t*)&h;
}
__device__ __forceinline__ void st2(float* p, float a, float b) {
    float2 v = { a, b }; *(float2*)p = v;
}
__device__ __forceinline__ void st2(__half* p, float a, float b) {
    *(uint32_t*)p = pack_h2(a, b);
}

// ---------------------------------------------------------------------------
// prep kernels
// ---------------------------------------------------------------------------
__global__ __launch_bounds__(256) void round_kernel(
    const float* __restrict__ src, __half* __restrict__ dst, size_t n4)
{
    size_t i = ((size_t)blockIdx.x * blockDim.x + threadIdx.x) * 2;
    size_t stride = (size_t)gridDim.x * blockDim.x * 2;
    for (; i < n4; i += stride) {
        float4 x = ((const float4*)src)[i];
        float4 y = ((const float4*)src)[i + 1];
        ((__half2*)dst)[i * 2]     = __floats2half2_rn(x.x, x.y);
        ((__half2*)dst)[i * 2 + 1] = __floats2half2_rn(x.z, x.w);
        ((__half2*)dst)[i * 2 + 2] = __floats2half2_rn(y.x, y.y);
        ((__half2*)dst)[i * 2 + 3] = __floats2half2_rn(y.z, y.w);
    }
}

__global__ __launch_bounds__(256) void transpose_f16_tiled(
    const float* __restrict__ W, __half* __restrict__ th)
{
    __shared__ float t[32][33];
    const int kb = blockIdx.x * 32, nb = blockIdx.y * 32;
    const int tx = threadIdx.x & 31, ty = threadIdx.x >> 5;
    #pragma unroll
    for (int i = ty; i < 32; i += 8)
        t[i][tx] = W[(size_t)(kb + i) * CQ + nb + tx];
    __syncthreads();
    #pragma unroll
    for (int i = ty; i < 32; i += 8)
        th[(size_t)(nb + i) * CKV + kb + tx] = __float2half_rn(t[tx][i]);
}

__global__ __launch_bounds__(256) void transpose_split768_tiled(
    const float* __restrict__ W, __half* __restrict__ th, __half* __restrict__ tl)
{
    __shared__ float t[32][33];
    const int kb = blockIdx.x * 32, nb = blockIdx.y * 32;
    const int tx = threadIdx.x & 31, ty = threadIdx.x >> 5;
    #pragma unroll
    for (int i = ty; i < 32; i += 8)
        t[i][tx] = W[(size_t)(kb + i) * CQ + nb + tx];
    __syncthreads();
    #pragma unroll
    for (int i = ty; i < 32; i += 8) {
        float x = t[tx][i];
        __half h = __float2half_rn(x);
        th[(size_t)(nb + i) * CQ + kb + tx] = h;
        tl[(size_t)(nb + i) * CQ + kb + tx] = __float2half_rn(x - __half2float(h));
    }
}

// ---------------------------------------------------------------------------
// Fused K+V HMMA fp16 GEMM, k-chunk 64 (CTA 128x128x64, 8 warps, occ 2)
// ---------------------------------------------------------------------------
#define GR_STRIDE 144
#define TILE_B (128 * GR_STRIDE)
#define STAGE_B (2 * TILE_B)
#define STAGES 3
#define HGEMM_SMEM (STAGES * STAGE_B)
#define KT_N (CKV / 64)

__global__ __launch_bounds__(256, 2) void hgemm_kv(
    const __half* __restrict__ A_g, const __half* __restrict__ Bkv,
    const float* __restrict__ bk, const float* __restrict__ bv,
    __half* __restrict__ Kout, __half* __restrict__ Vout)
{
    extern __shared__ char smem[];
    const uint32_t sbase = smem_u32(smem);
    const int tid = threadIdx.x;
    const int wid = tid >> 5, lane = tid & 31;
    const int wm = (wid & 1) * 64;
    const int wn = (wid >> 1) * 32;
    const int m0 = blockIdx.y * 128, n0 = blockIdx.x * 128;

    const int l_row = tid >> 3;
    const int l_c16 = tid & 7;
    const uint32_t l_soff = (uint32_t)(l_row * GR_STRIDE + l_c16 * 16);

    const int a_row = lane & 15;
    const int a_ko  = ((lane >> 4) & 1) * 8;
    const int b_row = (lane & 7) + ((lane >> 4) & 1) * 8;
    const int b_ko  = ((lane >> 3) & 1) * 8;

    float acc[4][4][4];
    #pragma unroll
    for (int i = 0; i < 4; i++)
        #pragma unroll
        for (int j = 0; j < 4; j++)
            #pragma unroll
            for (int c = 0; c < 4; c++) acc[i][j][c] = 0.f;

    auto load_stage = [&](int kt, int s) {
        const uint32_t sb = sbase + s * STAGE_B;
        const int ke = kt * 64;
        #pragma unroll
        for (int j = 0; j < 4; j++) {
            const int row = l_row + j * 32;
            const uint32_t so = l_soff + (uint32_t)(j * 32 * GR_STRIDE);
            cp16(sb + so,          A_g + (size_t)(m0 + row) * CKV + ke + l_c16 * 8);
            cp16(sb + TILE_B + so, Bkv + (size_t)(n0 + row) * CKV + ke + l_c16 * 8);
        }
        CP_COMMIT();
    };

    load_stage(0, 0);
    load_stage(1, 1);

    for (int kt = 0; kt < KT_N; kt++) {
        CP_WAIT(1);
        __syncthreads();

        const int nkt = kt + STAGES - 1;
        if (nkt < KT_N) load_stage(nkt, nkt % STAGES);
        else CP_COMMIT();

        const uint32_t sb = sbase + (kt % STAGES) * STAGE_B;
        #pragma unroll
        for (int kb = 0; kb < 64; kb += 16) {
            uint32_t ah[4][4];
            #pragma unroll
            for (int mt = 0; mt < 4; mt++) {
                uint32_t ra = sb + (uint32_t)((wm + mt * 16 + a_row) * GR_STRIDE
                                              + (a_ko + kb) * 2);
                ldsm_x4(ra, ah[mt][0], ah[mt][1], ah[mt][2], ah[mt][3]);
            }
            uint32_t bh[4][2];
            #pragma unroll
            for (int np = 0; np < 2; np++) {
                uint32_t rb = sb + TILE_B +
                              (uint32_t)((wn + np * 16 + b_row) * GR_STRIDE
                                         + (b_ko + kb) * 2);
                ldsm_x4(rb, bh[np * 2][0], bh[np * 2][1], bh[np * 2 + 1][0], bh[np * 2 + 1][1]);
            }
            #pragma unroll
            for (int mt = 0; mt < 4; mt++)
                #pragma unroll
                for (int nt = 0; nt < 4; nt++)
                    mma_f16(acc[mt][nt], ah[mt][0], ah[mt][1], ah[mt][2], ah[mt][3],
                            bh[nt][0], bh[nt][1]);
        }
    }

    const bool isV = (n0 >= CQ);
    const float* bias = isV ? bv : bk;
    __half* C = isV ? Vout : Kout;
    const int nc0 = isV ? (n0 - CQ) : n0;

    const int er = lane >> 2, ec = (lane & 3) * 2;
    #pragma unroll
    for (int mt = 0; mt < 4; mt++) {
        #pragma unroll
        for (int nt = 0; nt < 4; nt++) {
            const int col = nc0 + wn + nt * 8 + ec;
            const float b0 = bias[col], b1 = bias[col + 1];
            __half* p0 = C + (size_t)(m0 + wm + mt * 16 + er) * CQ + col;
            __half* p1 = p0 + 8 * CQ;
            st2(p0, acc[mt][nt][0] + b0, acc[mt][nt][1] + b1);
            st2(p1, acc[mt][nt][2] + b0, acc[mt][nt][3] + b1);
        }
    }
}

// ---------------------------------------------------------------------------
// Small HMMA fp16x2 GEMM (Q / O projections)
// ---------------------------------------------------------------------------
#define QO_TILE_B 5120
#define QO_STAGE_B (3 * QO_TILE_B)
#define QO_STAGES 3
#define QO_KT (CQ / 32)

template <typename OutT>
__global__ __launch_bounds__(128) void hgemm_qo(
    const __half* __restrict__ A_g, const __half* __restrict__ Bh_g,
    const __half* __restrict__ Bl_g, const float* __restrict__ bias,
    OutT* __restrict__ C)
{
    __shared__ char smem[QO_STAGES * QO_STAGE_B];
    const uint32_t sbase = smem_u32(smem);
    const int tid = threadIdx.x;
    const int wid = tid >> 5, lane = tid & 31;
    const int wm = (wid & 1) * 32;
    const int wn = (wid >> 1) * 32;
    const int m0 = blockIdx.y * 64, n0 = blockIdx.x * 64;

    const int lr = tid >> 1;
    const int lc = (tid & 1) * 16;
    const uint32_t s_off = (uint32_t)(lr * 80 + (tid & 1) * 32);

    const __half* gA  = A_g  + (size_t)(m0 + lr) * CQ + lc;
    const __half* gBh = Bh_g + (size_t)(n0 + lr) * CQ + lc;
    const __half* gBl = Bl_g + (size_t)(n0 + lr) * CQ + lc;

    const int a_row = lane & 15;
    const int a_ko  = ((lane >> 4) & 1) * 8;
    const int b_row = (lane & 7) + ((lane >> 4) & 1) * 8;
    const int b_ko  = ((lane >> 3) & 1) * 8;

    float acc[2][4][4];
    #pragma unroll
    for (int i = 0; i < 2; i++)
        #pragma unroll
        for (int j = 0; j < 4; j++)
            #pragma unroll
            for (int c = 0; c < 4; c++) acc[i][j][c] = 0.f;

    auto load_stage = [&](int kt, int s) {
        const uint32_t sb = sbase + s * QO_STAGE_B;
        const int ke = kt * 32;
        cp16(sb + s_off,                    gA  + ke);
        cp16(sb + s_off + 16,               gA  + ke + 8);
        cp16(sb + QO_TILE_B + s_off,        gBh + ke);
        cp16(sb + QO_TILE_B + s_off + 16,   gBh + ke + 8);
        cp16(sb + 2*QO_TILE_B + s_off,      gBl + ke);
        cp16(sb + 2*QO_TILE_B + s_off + 16, gBl + ke + 8);
    };

    load_stage(0, 0); CP_COMMIT();
    load_stage(1, 1); CP_COMMIT();

    for (int kt = 0; kt < QO_KT; kt++) {
        CP_WAIT(1);
        __syncthreads();

        const int nkt = kt + QO_STAGES - 1;
        if (nkt < QO_KT) load_stage(nkt, nkt % QO_STAGES);
        CP_COMMIT();

        const uint32_t sb = sbase + (kt % QO_STAGES) * QO_STAGE_B;
        #pragma unroll
        for (int kb = 0; kb < 32; kb += 16) {
            uint32_t a[2][4];
            #pragma unroll
            for (int mt = 0; mt < 2; mt++) {
                uint32_t ra = sb + (uint32_t)((wm + mt * 16 + a_row) * 80 + (a_ko + kb) * 2);
                ldsm_x4(ra, a[mt][0], a[mt][1], a[mt][2], a[mt][3]);
            }
            uint32_t bh[4][2], bl[4][2];
            #pragma unroll
            for (int ng = 0; ng < 2; ng++) {
                uint32_t rbh = sb + QO_TILE_B +
                               (uint32_t)((wn + ng * 16 + b_row) * 80 + (b_ko + kb) * 2);
                ldsm_x4(rbh, bh[2*ng][0], bh[2*ng][1], bh[2*ng+1][0], bh[2*ng+1][1]);
                ldsm_x4(rbh + QO_TILE_B, bl[2*ng][0], bl[2*ng][1], bl[2*ng+1][0], bl[2*ng+1][1]);
            }
            #pragma unroll
            for (int mt = 0; mt < 2; mt++)
                #pragma unroll
                for (int nt = 0; nt < 4; nt++) {
                    mma_f16(acc[mt][nt], a[mt][0], a[mt][1], a[mt][2], a[mt][3],
                            bh[nt][0], bh[nt][1]);
                    mma_f16(acc[mt][nt], a[mt][0], a[mt][1], a[mt][2], a[mt][3],
                            bl[nt][0], bl[nt][1]);
                }
        }
    }

    const int er = lane >> 2, ec = (lane & 3) * 2;
    #pragma unroll
    for (int mt = 0; mt < 2; mt++) {
        #pragma unroll
        for (int nt = 0; nt < 4; nt++) {
            const int col = n0 + wn + nt * 8 + ec;
            const float b0 = bias[col], b1 = bias[col + 1];
            OutT* p0 = C + (size_t)(m0 + wm + mt * 16 + er) * CQ + col;
            OutT* p1 = p0 + 8 * CQ;
            st2(p0, acc[mt][nt][0] + b0, acc[mt][nt][1] + b1);
            st2(p1, acc[mt][nt][2] + b0, acc[mt][nt][3] + b1);
        }
    }
}

// ---------------------------------------------------------------------------
// HMMA split-KV flash attention with FUSED combine:
// last-arriving split CTA of each bh performs the combine inline.
// ---------------------------------------------------------------------------
#define KV_PER_SPLIT (NKV / SPLIT)      // 1024
#define N_CHUNKS (KV_PER_SPLIT / 64)    // 16

__global__ __launch_bounds__(128) void attention_hmma(
    const __half* __restrict__ Qg, const __half* __restrict__ Kg,
    const __half* __restrict__ Vg,
    float* __restrict__ accP, float* __restrict__ mP, float* __restrict__ lP,
    unsigned int* __restrict__ cnt, __half* __restrict__ Xg)
{
    __shared__ __half Qs[64][72];
    __shared__ __half Ks[2][64][72];
    __shared__ __half Vs[2][64][72];
    __shared__ unsigned int s_last;

    const int gidx = blockIdx.x;
    const int bh = gidx / SPLIT;
    const int sp = gidx % SPLIT;
    const int b = bh / H_, h = bh % H_;
    const int tid = threadIdx.x;
    const int w = tid >> 5, lane = tid & 31;
    const int kv_lo = sp * KV_PER_SPLIT;

    auto load_chunk = [&](int c, int buf) {
        const int kv0 = kv_lo + c * 64;
        #pragma unroll
        for (int idx = tid; idx < 512; idx += 128) {
            int r = idx >> 3, sg = idx & 7;
            size_t gofs = (size_t)(b * NKV + kv0 + r) * CQ + h * D_ + sg * 8;
            cp16(smem_u32(&Ks[buf][r][sg * 8]), Kg + gofs);
            cp16(smem_u32(&Vs[buf][r][sg * 8]), Vg + gofs);
        }
        CP_COMMIT();
    };

    load_chunk(0, 0);

    {
        const __half2 sc = __floats2half2_rn(0.125f, 0.125f);
        for (int idx = tid; idx < 512; idx += 128) {
            int r = idx >> 3, c8 = (idx & 7) * 8;
            uint4 v = *(const uint4*)(Qg + (size_t)(b * NQ + r) * CQ + h * D_ + c8);
            __half2* s = (__half2*)&v;
            __half2* d = (__half2*)&Qs[r][c8];
            d[0] = __hmul2(s[0], sc); d[1] = __hmul2(s[1], sc);
            d[2] = __hmul2(s[2], sc); d[3] = __hmul2(s[3], sc);
        }
    }

    const int qa_row = lane & 15;
    const int qa_ko  = ((lane >> 4) & 1) * 8;
    const int kb_row = (lane & 7) + ((lane >> 4) & 1) * 8;
    const int kb_ko  = ((lane >> 3) & 1) * 8;
    const int vt_row = (lane & 7) + ((lane >> 3) & 1) * 8;
    const int vt_co  = ((lane >> 4) & 1) * 8;

    float m0 = -1e30f, m1 = -1e30f, l0 = 0.f, l1 = 0.f;
    float o[8][4];
    #pragma unroll
    for (int i = 0; i < 8; i++)
        #pragma unroll
        for (int j = 0; j < 4; j++) o[i][j] = 0.f;

    for (int c = 0; c < N_CHUNKS; c++) {
        const int cur = c & 1;
        if (c + 1 < N_CHUNKS) { load_chunk(c + 1, cur ^ 1); CP_WAIT(1); }
        else                  { CP_WAIT(0); }
        __syncthreads();

        float s[8][4];
        #pragma unroll
        for (int i = 0; i < 8; i++)
            #pragma unroll
            for (int j = 0; j < 4; j++) s[i][j] = 0.f;

        #pragma unroll
        for (int kk = 0; kk < 4; kk++) {
            uint32_t a0, a1, a2, a3;
            ldsm_x4(smem_u32(&Qs[w * 16 + qa_row][kk * 16 + qa_ko]), a0, a1, a2, a3);
            #pragma unroll
            for (int ng = 0; ng < 4; ng++) {
                uint32_t b0, b1, b2, b3;
                ldsm_x4(smem_u32(&Ks[cur][ng * 16 + kb_row][kk * 16 + kb_ko]),
                        b0, b1, b2, b3);
                mma_f16(s[2 * ng],     a0, a1, a2, a3, b0, b1);
                mma_f16(s[2 * ng + 1], a0, a1, a2, a3, b2, b3);
            }
        }

        float mx0 = -1e30f, mx1 = -1e30f;
        #pragma unroll
        for (int nt = 0; nt < 8; nt++) {
            mx0 = fmaxf(mx0, fmaxf(s[nt][0], s[nt][1]));
            mx1 = fmaxf(mx1, fmaxf(s[nt][2], s[nt][3]));
        }
        #pragma unroll
        for (int ofs = 1; ofs < 4; ofs <<= 1) {
            mx0 = fmaxf(mx0, __shfl_xor_sync(0xffffffffu, mx0, ofs));
            mx1 = fmaxf(mx1, __shfl_xor_sync(0xffffffffu, mx1, ofs));
        }
        float M0 = fmaxf(m0, mx0), M1 = fmaxf(m1, mx1);
        float c0 = __expf(m0 - M0), c1 = __expf(m1 - M1);
        float ls0 = 0.f, ls1 = 0.f;
        #pragma unroll
        for (int nt = 0; nt < 8; nt++) {
            s[nt][0] = __expf(s[nt][0] - M0); ls0 += s[nt][0];
            s[nt][1] = __expf(s[nt][1] - M0); ls0 += s[nt][1];
            s[nt][2] = __expf(s[nt][2] - M1); ls1 += s[nt][2];
            s[nt][3] = __expf(s[nt][3] - M1); ls1 += s[nt][3];
        }
        #pragma unroll
        for (int ofs = 1; ofs < 4; ofs <<= 1) {
            ls0 += __shfl_xor_sync(0xffffffffu, ls0, ofs);
            ls1 += __shfl_xor_sync(0xffffffffu, ls1, ofs);
        }
        l0 = l0 * c0 + ls0;  l1 = l1 * c1 + ls1;
        m0 = M0;  m1 = M1;
        #pragma unroll
        for (int nt = 0; nt < 8; nt++) {
            o[nt][0] *= c0; o[nt][1] *= c0;
            o[nt][2] *= c1; o[nt][3] *= c1;
        }

        uint32_t pu[8][2];
        #pragma unroll
        for (int nt = 0; nt < 8; nt++) {
            pu[nt][0] = pack_h2(s[nt][0], s[nt][1]);
            pu[nt][1] = pack_h2(s[nt][2], s[nt][3]);
        }

        #pragma unroll
        for (int t = 0; t < 4; t++) {
            uint32_t a0 = pu[2 * t][0],     a1 = pu[2 * t][1];
            uint32_t a2 = pu[2 * t + 1][0], a3 = pu[2 * t + 1][1];
            #pragma unroll
            for (int dg = 0; dg < 4; dg++) {
                uint32_t b0, b1, b2, b3;
                ldsm_x4_t(smem_u32(&Vs[cur][t * 16 + vt_row][dg * 16 + vt_co]),
                          b0, b1, b2, b3);
                mma_f16(o[2 * dg],     a0, a1, a2, a3, b0, b1);
                mma_f16(o[2 * dg + 1], a0, a1, a2, a3, b2, b3);
            }
        }
        __syncthreads();
    }

    // write unnormalized partials
    float* accp = accP + (size_t)gidx * 64 * 64;
    const int r0 = w * 16 + (lane >> 2), r1 = r0 + 8;
    const int cb = (lane & 3) * 2;
    #pragma unroll
    for (int nt = 0; nt < 8; nt++) {
        st2(&accp[r0 * 64 + nt * 8 + cb], o[nt][0], o[nt][1]);
        st2(&accp[r1 * 64 + nt * 8 + cb], o[nt][2], o[nt][3]);
    }
    if ((lane & 3) == 0) {
        mP[(size_t)gidx * 64 + r0] = m0;
        lP[(size_t)gidx * 64 + r0] = l0;
        mP[(size_t)gidx * 64 + r1] = m1;
        lP[(size_t)gidx * 64 + r1] = l1;
    }

    // ---- fused combine: last-arriving split CTA of this bh does it ----
    __threadfence();
    __syncthreads();
    if (tid == 0) {
        unsigned int old = atomicAdd(&cnt[bh], 1u);
        s_last = ((old % SPLIT) == SPLIT - 1) ? 1u : 0u;
    }
    __syncthreads();
    if (!s_last) return;
    __threadfence();   // acquire: other CTAs' partials now visible

    __shared__ float sw[SPLIT][64];
    __shared__ float sden[64];
    if (tid < 64) {
        int r = tid;
        float M = -1e30f;
        #pragma unroll
        for (int s = 0; s < SPLIT; s++)
            M = fmaxf(M, mP[(size_t)(bh * SPLIT + s) * 64 + r]);
        float den = 0.f;
        #pragma unroll
        for (int s = 0; s < SPLIT; s++) {
            float wgt = __expf(mP[(size_t)(bh * SPLIT + s) * 64 + r] - M);
            sw[s][r] = wgt;
            den += wgt * lP[(size_t)(bh * SPLIT + s) * 64 + r];
        }
        sden[r] = den;
    }
    __syncthreads();

    const float* accb = accP + (size_t)bh * SPLIT * 4096;
    for (int idx = tid; idx < 64 * 64; idx += 128) {
        int r = idx >> 6, d = idx & 63;
        float num = 0.f;
        #pragma unroll
        for (int s = 0; s < SPLIT; s++)
            num += sw[s][r] * accb[s * 4096 + idx];
        Xg[(size_t)(b * NQ + r) * CQ + h * D_ + d] = __float2half_rn(num / sden[r]);
    }
}

// ---------------------------------------------------------------------------
extern "C" void kernel_launch(void* const* d_in, const int* in_sizes, int n_in,
                              void* d_out, int out_size)
{
    const float* query = (const float*)d_in[0];
    const float* kv    = (const float*)d_in[1];
    const float* Wq    = (const float*)d_in[2];
    const float* bq    = (const float*)d_in[3];
    const float* Wk    = (const float*)d_in[4];
    const float* bk    = (const float*)d_in[5];
    const float* Wv    = (const float*)d_in[6];
    const float* bv    = (const float*)d_in[7];
    const float* Wo    = (const float*)d_in[8];
    const float* bo    = (const float*)d_in[9];
    float* out = (float*)d_out;

    float *accp, *mp, *lp;
    unsigned int* cntp;
    __half *qa, *qh, *xh, *kp, *vp, *kva, *wkvt, *wqth, *wqtl, *woth, *wotl;
    cudaGetSymbolAddress((void**)&qa, g_qa);
    cudaGetSymbolAddress((void**)&qh, g_qh);
    cudaGetSymbolAddress((void**)&xh, g_xh);
    cudaGetSymbolAddress((void**)&kp, g_kh);
    cudaGetSymbolAddress((void**)&vp, g_vh);
    cudaGetSymbolAddress((void**)&kva, g_kva);
    cudaGetSymbolAddress((void**)&wkvt, g_wkvt);
    cudaGetSymbolAddress((void**)&wqth, g_wqth);
    cudaGetSymbolAddress((void**)&wqtl, g_wqtl);
    cudaGetSymbolAddress((void**)&woth, g_woth);
    cudaGetSymbolAddress((void**)&wotl, g_wotl);
    cudaGetSymbolAddress((void**)&accp, g_accP);
    cudaGetSymbolAddress((void**)&mp, g_mP);
    cudaGetSymbolAddress((void**)&lp, g_lP);
    cudaGetSymbolAddress((void**)&cntp, g_cnt);

    cudaFuncSetAttribute(hgemm_kv,
                         cudaFuncAttributeMaxDynamicSharedMemorySize, HGEMM_SMEM);

    const size_t M_Q     = (size_t)B_ * NKV / 4;
    const size_t ELEMS_Q = M_Q * CKV;
    const size_t N4_Q    = ELEMS_Q / 4;
    const size_t M_H     = (size_t)B_ * NKV / 2;
    const size_t ELEMS_H = M_H * CKV;
    const size_t C_H     = M_H * CQ;
    const dim3 GEMM_GRID(2 * CQ / 128, (unsigned)(M_H / 128));

    int prLo, prHi;
    cudaDeviceGetStreamPriorityRange(&prLo, &prHi);
    cudaStream_t s2;
    cudaStreamCreateWithPriority(&s2, cudaStreamNonBlocking, prHi);
    cudaEvent_t eFork, eW, eR01, eR23, eJoin;
    cudaEventCreateWithFlags(&eFork, cudaEventDisableTiming);
    cudaEventCreateWithFlags(&eW, cudaEventDisableTiming);
    cudaEventCreateWithFlags(&eR01, cudaEventDisableTiming);
    cudaEventCreateWithFlags(&eR23, cudaEventDisableTiming);
    cudaEventCreateWithFlags(&eJoin, cudaEventDisableTiming);

    cudaEventRecord(eFork, 0);
    cudaStreamWaitEvent(s2, eFork, 0);

    // main: round quarter 0
    round_kernel<<<1024, 256>>>(kv, kva, N4_Q);

    // side: weight transposes, rounds q1..q3, q path
    transpose_f16_tiled<<<dim3(CKV / 32, CQ / 32), 256, 0, s2>>>(Wk, wkvt);
    transpose_f16_tiled<<<dim3(CKV / 32, CQ / 32), 256, 0, s2>>>(Wv, wkvt + (size_t)CQ * CKV);
    cudaEventRecord(eW, s2);
    round_kernel<<<1024, 256, 0, s2>>>(kv + ELEMS_Q, kva + ELEMS_Q, N4_Q);
    cudaEventRecord(eR01, s2);
    round_kernel<<<1024, 256, 0, s2>>>(kv + 2 * ELEMS_Q, kva + 2 * ELEMS_Q, N4_Q);
    round_kernel<<<1024, 256, 0, s2>>>(kv + 3 * ELEMS_Q, kva + 3 * ELEMS_Q, N4_Q);
    cudaEventRecord(eR23, s2);
    round_kernel<<<384, 256, 0, s2>>>(query, qa, (size_t)B_ * NQ * CQ / 4);
    transpose_split768_tiled<<<dim3(CQ / 32, CQ / 32), 256, 0, s2>>>(Wq, wqth, wqtl);
    transpose_split768_tiled<<<dim3(CQ / 32, CQ / 32), 256, 0, s2>>>(Wo, woth, wotl);
    hgemm_qo<__half><<<dim3(CQ / 64, (B_ * NQ) / 64), 128, 0, s2>>>(qa, wqth, wqtl, bq, qh);
    cudaEventRecord(eJoin, s2);

    // main: K/V projection in 2 m-halves
    cudaStreamWaitEvent(0, eW, 0);
    cudaStreamWaitEvent(0, eR01, 0);
    hgemm_kv<<<GEMM_GRID, 256, HGEMM_SMEM>>>(kva, wkvt, bk, bv, kp, vp);
    cudaStreamWaitEvent(0, eR23, 0);
    hgemm_kv<<<GEMM_GRID, 256, HGEMM_SMEM>>>(kva + ELEMS_H, wkvt, bk, bv,
                                             kp + C_H, vp + C_H);

    // join q path, then fused attention+combine, then output projection
    cudaStreamWaitEvent(0, eJoin, 0);
    attention_hmma<<<B_ * H_ * SPLIT, 128>>>(qh, kp, vp, accp, mp, lp, cntp, xh);
    hgemm_qo<float><<<dim3(CQ / 64, (B_ * NQ) / 64), 128>>>(xh, woth, wotl, bo, out);

    cudaEventDestroy(eFork);
    cudaEventDestroy(eW);
    cudaEventDestroy(eR01);
    cudaEventDestroy(eR23);
    cudaEventDestroy(eJoin);
    cudaStreamDestroy(s2);
}

// round 16
// speedup vs baseline: 1.0083x; 1.0083x over previous
#include <cuda_runtime.h>
#include <cuda_bf16.h>
#include <cuda_fp16.h>
#include <math.h>
#include <stdint.h>

#define B_   16
#define NQ   64
#define NKV  4096
#define CQ   768
#define CKV  1024
#define H_   12
#define D_   64
#define SPLIT 8

// ---------------- scratch (device globals; allocation-free) ----------------
__device__ __half g_qa  [(size_t)B_ * NQ * CQ];
__device__ __half g_qh  [(size_t)B_ * NQ * CQ];
__device__ __half g_xh  [(size_t)B_ * NQ * CQ];
__device__ __half g_kh  [(size_t)B_ * NKV * CQ];
__device__ __half g_vh  [(size_t)B_ * NKV * CQ];
__device__ __half g_kva [(size_t)B_ * NKV * CKV];
__device__ __half g_wkvt[(size_t)2 * CQ * CKV];
__device__ __half g_wqth[(size_t)CQ * CQ];
__device__ __half g_wqtl[(size_t)CQ * CQ];
__device__ __half g_woth[(size_t)CQ * CQ];
__device__ __half g_wotl[(size_t)CQ * CQ];
__device__ float g_accP[(size_t)B_ * H_ * SPLIT * NQ * D_];
__device__ float g_mP[(size_t)B_ * H_ * SPLIT * NQ];
__device__ float g_lP[(size_t)B_ * H_ * SPLIT * NQ];

// ---------------- helpers ----------------
__device__ __forceinline__ uint32_t smem_u32(const void* p) {
    uint32_t a;
    asm("{ .reg .u64 t; cvta.to.shared.u64 t, %1; cvt.u32.u64 %0, t; }"
        : "=r"(a) : "l"(p));
    return a;
}
__device__ __forceinline__ void cp16(uint32_t s, const void* g) {
    asm volatile("cp.async.cg.shared.global [%0], [%1], 16;\n"
                 :: "r"(s), "l"(__cvta_generic_to_global(g)) : "memory");
}
#define CP_COMMIT() asm volatile("cp.async.commit_group;\n" ::: "memory")
#define CP_WAIT(n)  asm volatile("cp.async.wait_group %0;\n" :: "n"(n) : "memory")

__device__ __forceinline__ void ldsm_x4(uint32_t addr, uint32_t& r0, uint32_t& r1,
                                        uint32_t& r2, uint32_t& r3) {
    asm volatile("ldmatrix.sync.aligned.m8n8.x4.shared.b16 {%0,%1,%2,%3}, [%4];"
                 : "=r"(r0), "=r"(r1), "=r"(r2), "=r"(r3) : "r"(addr));
}
__device__ __forceinline__ void ldsm_x4_t(uint32_t addr, uint32_t& r0, uint32_t& r1,
                                          uint32_t& r2, uint32_t& r3) {
    asm volatile("ldmatrix.sync.aligned.m8n8.x4.trans.shared.b16 {%0,%1,%2,%3}, [%4];"
                 : "=r"(r0), "=r"(r1), "=r"(r2), "=r"(r3) : "r"(addr));
}
__device__ __forceinline__ void mma_f16(float* d, uint32_t a0, uint32_t a1,
                                        uint32_t a2, uint32_t a3,
                                        uint32_t b0, uint32_t b1) {
    asm volatile(
        "mma.sync.aligned.m16n8k16.row.col.f32.f16.f16.f32 "
        "{%0,%1,%2,%3}, {%4,%5,%6,%7}, {%8,%9}, {%0,%1,%2,%3};"
        : "+f"(d[0]), "+f"(d[1]), "+f"(d[2]), "+f"(d[3])
        : "r"(a0), "r"(a1), "r"(a2), "r"(a3), "r"(b0), "r"(b1));
}
__device__ __forceinline__ uint32_t pack_h2(float a, float b) {
    __half2 h = __floats2half2_rn(a, b);
    return *(uint32_t*)&h;
}
__device__ __forceinline__ void st2(float* p, float a, float b) {
    float2 v = { a, b }; *(float2*)p = v;
}
__device__ __forceinline__ void st2(__half* p, float a, float b) {
    *(uint32_t*)p = pack_h2(a, b);
}

// ---------------------------------------------------------------------------
// prep kernels
// ---------------------------------------------------------------------------
__global__ __launch_bounds__(256) void round_kernel(
    const float* __restrict__ src, __half* __restrict__ dst, size_t n4)
{
    size_t i = ((size_t)blockIdx.x * blockDim.x + threadIdx.x) * 2;
    size_t stride = (size_t)gridDim.x * blockDim.x * 2;
    for (; i < n4; i += stride) {
        float4 x = ((const float4*)src)[i];
        float4 y = ((const float4*)src)[i + 1];
        ((__half2*)dst)[i * 2]     = __floats2half2_rn(x.x, x.y);
        ((__half2*)dst)[i * 2 + 1] = __floats2half2_rn(x.z, x.w);
        ((__half2*)dst)[i * 2 + 2] = __floats2half2_rn(y.x, y.y);
        ((__half2*)dst)[i * 2 + 3] = __floats2half2_rn(y.z, y.w);
    }
}

__global__ __launch_bounds__(256) void transpose_f16_tiled(
    const float* __restrict__ W, __half* __restrict__ th)
{
    __shared__ float t[32][33];
    const int kb = blockIdx.x * 32, nb = blockIdx.y * 32;
    const int tx = threadIdx.x & 31, ty = threadIdx.x >> 5;
    #pragma unroll
    for (int i = ty; i < 32; i += 8)
        t[i][tx] = W[(size_t)(kb + i) * CQ + nb + tx];
    __syncthreads();
    #pragma unroll
    for (int i = ty; i < 32; i += 8)
        th[(size_t)(nb + i) * CKV + kb + tx] = __float2half_rn(t[tx][i]);
}

__global__ __launch_bounds__(256) void transpose_split768_tiled(
    const float* __restrict__ W, __half* __restrict__ th, __half* __restrict__ tl)
{
    __shared__ float t[32][33];
    const int kb = blockIdx.x * 32, nb = blockIdx.y * 32;
    const int tx = threadIdx.x & 31, ty = threadIdx.x >> 5;
    #pragma unroll
    for (int i = ty; i < 32; i += 8)
        t[i][tx] = W[(size_t)(kb + i) * CQ + nb + tx];
    __syncthreads();
    #pragma unroll
    for (int i = ty; i < 32; i += 8) {
        float x = t[tx][i];
        __half h = __float2half_rn(x);
        th[(size_t)(nb + i) * CQ + kb + tx] = h;
        tl[(size_t)(nb + i) * CQ + kb + tx] = __float2half_rn(x - __half2float(h));
    }
}

// ---------------------------------------------------------------------------
// Fused K+V HMMA fp16 GEMM, k-chunk 64: [K|V] = A16 [Wk^T;Wv^T] + bias.
// CTA 128x128x64, 8 warps, 3-stage cp.async, occupancy 2.
// Row stride 144 B (16B pad): ldmatrix conflict-free (144 mod 128 = 16).
// ---------------------------------------------------------------------------
#define GR_STRIDE 144
#define TILE_B (128 * GR_STRIDE)      // 18432
#define STAGE_B (2 * TILE_B)          // 36864
#define STAGES 3
#define HGEMM_SMEM (STAGES * STAGE_B) // 110592
#define KT_N (CKV / 64)               // 16

__global__ __launch_bounds__(256, 2) void hgemm_kv(
    const __half* __restrict__ A_g, const __half* __restrict__ Bkv,
    const float* __restrict__ bk, const float* __restrict__ bv,
    __half* __restrict__ Kout, __half* __restrict__ Vout)
{
    extern __shared__ char smem[];
    const uint32_t sbase = smem_u32(smem);
    const int tid = threadIdx.x;
    const int wid = tid >> 5, lane = tid & 31;
    const int wm = (wid & 1) * 64;
    const int wn = (wid >> 1) * 32;
    const int m0 = blockIdx.y * 128, n0 = blockIdx.x * 128;

    // loader mapping: 8 x 16B segments per 128B row chunk; 4 row-steps per thread
    const int l_row = tid >> 3;          // rows 0..31 (x4 j-steps -> 0..127)
    const int l_c16 = tid & 7;
    const uint32_t l_soff = (uint32_t)(l_row * GR_STRIDE + l_c16 * 16);

    const int a_row = lane & 15;
    const int a_ko  = ((lane >> 4) & 1) * 8;
    const int b_row = (lane & 7) + ((lane >> 4) & 1) * 8;
    const int b_ko  = ((lane >> 3) & 1) * 8;

    float acc[4][4][4];
    #pragma unroll
    for (int i = 0; i < 4; i++)
        #pragma unroll
        for (int j = 0; j < 4; j++)
            #pragma unroll
            for (int c = 0; c < 4; c++) acc[i][j][c] = 0.f;

    auto load_stage = [&](int kt, int s) {
        const uint32_t sb = sbase + s * STAGE_B;
        const int ke = kt * 64;
        #pragma unroll
        for (int j = 0; j < 4; j++) {
            const int row = l_row + j * 32;
            const uint32_t so = l_soff + (uint32_t)(j * 32 * GR_STRIDE);
            cp16(sb + so,          A_g + (size_t)(m0 + row) * CKV + ke + l_c16 * 8);
            cp16(sb + TILE_B + so, Bkv + (size_t)(n0 + row) * CKV + ke + l_c16 * 8);
        }
        CP_COMMIT();
    };

    load_stage(0, 0);
    load_stage(1, 1);

    for (int kt = 0; kt < KT_N; kt++) {
        CP_WAIT(1);
        __syncthreads();

        const int nkt = kt + STAGES - 1;
        if (nkt < KT_N) load_stage(nkt, nkt % STAGES);
        else CP_COMMIT();

        const uint32_t sb = sbase + (kt % STAGES) * STAGE_B;
        #pragma unroll
        for (int kb = 0; kb < 64; kb += 16) {
            uint32_t ah[4][4];
            #pragma unroll
            for (int mt = 0; mt < 4; mt++) {
                uint32_t ra = sb + (uint32_t)((wm + mt * 16 + a_row) * GR_STRIDE
                                              + (a_ko + kb) * 2);
                ldsm_x4(ra, ah[mt][0], ah[mt][1], ah[mt][2], ah[mt][3]);
            }
            uint32_t bh[4][2];
            #pragma unroll
            for (int np = 0; np < 2; np++) {
                uint32_t rb = sb + TILE_B +
                              (uint32_t)((wn + np * 16 + b_row) * GR_STRIDE
                                         + (b_ko + kb) * 2);
                ldsm_x4(rb, bh[np * 2][0], bh[np * 2][1], bh[np * 2 + 1][0], bh[np * 2 + 1][1]);
            }
            #pragma unroll
            for (int mt = 0; mt < 4; mt++)
                #pragma unroll
                for (int nt = 0; nt < 4; nt++)
                    mma_f16(acc[mt][nt], ah[mt][0], ah[mt][1], ah[mt][2], ah[mt][3],
                            bh[nt][0], bh[nt][1]);
        }
    }

    const bool isV = (n0 >= CQ);
    const float* bias = isV ? bv : bk;
    __half* C = isV ? Vout : Kout;
    const int nc0 = isV ? (n0 - CQ) : n0;

    const int er = lane >> 2, ec = (lane & 3) * 2;
    #pragma unroll
    for (int mt = 0; mt < 4; mt++) {
        #pragma unroll
        for (int nt = 0; nt < 4; nt++) {
            const int col = nc0 + wn + nt * 8 + ec;
            const float b0 = bias[col], b1 = bias[col + 1];
            __half* p0 = C + (size_t)(m0 + wm + mt * 16 + er) * CQ + col;
            __half* p1 = p0 + 8 * CQ;
            st2(p0, acc[mt][nt][0] + b0, acc[mt][nt][1] + b1);
            st2(p1, acc[mt][nt][2] + b0, acc[mt][nt][3] + b1);
        }
    }
}

// ---------------------------------------------------------------------------
// Small HMMA fp16x2 GEMM (Q / O projections)
// ---------------------------------------------------------------------------
#define QO_TILE_B 5120
#define QO_STAGE_B (3 * QO_TILE_B)
#define QO_STAGES 3
#define QO_KT (CQ / 32)

template <typename OutT>
__global__ __launch_bounds__(128) void hgemm_qo(
    const __half* __restrict__ A_g, const __half* __restrict__ Bh_g,
    const __half* __restrict__ Bl_g, const float* __restrict__ bias,
    OutT* __restrict__ C)
{
    __shared__ char smem[QO_STAGES * QO_STAGE_B];
    const uint32_t sbase = smem_u32(smem);
    const int tid = threadIdx.x;
    const int wid = tid >> 5, lane = tid & 31;
    const int wm = (wid & 1) * 32;
    const int wn = (wid >> 1) * 32;
    const int m0 = blockIdx.y * 64, n0 = blockIdx.x * 64;

    const int lr = tid >> 1;
    const int lc = (tid & 1) * 16;
    const uint32_t s_off = (uint32_t)(lr * 80 + (tid & 1) * 32);

    const __half* gA  = A_g  + (size_t)(m0 + lr) * CQ + lc;
    const __half* gBh = Bh_g + (size_t)(n0 + lr) * CQ + lc;
    const __half* gBl = Bl_g + (size_t)(n0 + lr) * CQ + lc;

    const int a_row = lane & 15;
    const int a_ko  = ((lane >> 4) & 1) * 8;
    const int b_row = (lane & 7) + ((lane >> 4) & 1) * 8;
    const int b_ko  = ((lane >> 3) & 1) * 8;

    float acc[2][4][4];
    #pragma unroll
    for (int i = 0; i < 2; i++)
        #pragma unroll
        for (int j = 0; j < 4; j++)
            #pragma unroll
            for (int c = 0; c < 4; c++) acc[i][j][c] = 0.f;

    auto load_stage = [&](int kt, int s) {
        const uint32_t sb = sbase + s * QO_STAGE_B;
        const int ke = kt * 32;
        cp16(sb + s_off,                    gA  + ke);
        cp16(sb + s_off + 16,               gA  + ke + 8);
        cp16(sb + QO_TILE_B + s_off,        gBh + ke);
        cp16(sb + QO_TILE_B + s_off + 16,   gBh + ke + 8);
        cp16(sb + 2*QO_TILE_B + s_off,      gBl + ke);
        cp16(sb + 2*QO_TILE_B + s_off + 16, gBl + ke + 8);
    };

    load_stage(0, 0); CP_COMMIT();
    load_stage(1, 1); CP_COMMIT();

    for (int kt = 0; kt < QO_KT; kt++) {
        CP_WAIT(1);
        __syncthreads();

        const int nkt = kt + QO_STAGES - 1;
        if (nkt < QO_KT) load_stage(nkt, nkt % QO_STAGES);
        CP_COMMIT();

        const uint32_t sb = sbase + (kt % QO_STAGES) * QO_STAGE_B;
        #pragma unroll
        for (int kb = 0; kb < 32; kb += 16) {
            uint32_t a[2][4];
            #pragma unroll
            for (int mt = 0; mt < 2; mt++) {
                uint32_t ra = sb + (uint32_t)((wm + mt * 16 + a_row) * 80 + (a_ko + kb) * 2);
                ldsm_x4(ra, a[mt][0], a[mt][1], a[mt][2], a[mt][3]);
            }
            uint32_t bh[4][2], bl[4][2];
            #pragma unroll
            for (int ng = 0; ng < 2; ng++) {
                uint32_t rbh = sb + QO_TILE_B +
                               (uint32_t)((wn + ng * 16 + b_row) * 80 + (b_ko + kb) * 2);
                ldsm_x4(rbh, bh[2*ng][0], bh[2*ng][1], bh[2*ng+1][0], bh[2*ng+1][1]);
                ldsm_x4(rbh + QO_TILE_B, bl[2*ng][0], bl[2*ng][1], bl[2*ng+1][0], bl[2*ng+1][1]);
            }
            #pragma unroll
            for (int mt = 0; mt < 2; mt++)
                #pragma unroll
                for (int nt = 0; nt < 4; nt++) {
                    mma_f16(acc[mt][nt], a[mt][0], a[mt][1], a[mt][2], a[mt][3],
                            bh[nt][0], bh[nt][1]);
                    mma_f16(acc[mt][nt], a[mt][0], a[mt][1], a[mt][2], a[mt][3],
                            bl[nt][0], bl[nt][1]);
                }
        }
    }

    const int er = lane >> 2, ec = (lane & 3) * 2;
    #pragma unroll
    for (int mt = 0; mt < 2; mt++) {
        #pragma unroll
        for (int nt = 0; nt < 4; nt++) {
            const int col = n0 + wn + nt * 8 + ec;
            const float b0 = bias[col], b1 = bias[col + 1];
            OutT* p0 = C + (size_t)(m0 + wm + mt * 16 + er) * CQ + col;
            OutT* p1 = p0 + 8 * CQ;
            st2(p0, acc[mt][nt][0] + b0, acc[mt][nt][1] + b1);
            st2(p1, acc[mt][nt][2] + b0, acc[mt][nt][3] + b1);
        }
    }
}

// ---------------------------------------------------------------------------
// HMMA split-KV flash attention partial, double-buffered K/V chunks
// ---------------------------------------------------------------------------
#define KV_PER_SPLIT (NKV / SPLIT)
#define N_CHUNKS (KV_PER_SPLIT / 64)

__global__ __launch_bounds__(128) void attention_hmma(
    const __half* __restrict__ Qg, const __half* __restrict__ Kg,
    const __half* __restrict__ Vg,
    float* __restrict__ accP, float* __restrict__ mP, float* __restrict__ lP)
{
    __shared__ __half Qs[64][72];
    __shared__ __half Ks[2][64][72];
    __shared__ __half Vs[2][64][72];

    const int bh = blockIdx.x / SPLIT;
    const int sp = blockIdx.x % SPLIT;
    const int b = bh / H_, h = bh % H_;
    const int tid = threadIdx.x;
    const int w = tid >> 5, lane = tid & 31;
    const int kv_lo = sp * KV_PER_SPLIT;

    auto load_chunk = [&](int c, int buf) {
        const int kv0 = kv_lo + c * 64;
        #pragma unroll
        for (int idx = tid; idx < 512; idx += 128) {
            int r = idx >> 3, sg = idx & 7;
            size_t gofs = (size_t)(b * NKV + kv0 + r) * CQ + h * D_ + sg * 8;
            cp16(smem_u32(&Ks[buf][r][sg * 8]), Kg + gofs);
            cp16(smem_u32(&Vs[buf][r][sg * 8]), Vg + gofs);
        }
        CP_COMMIT();
    };

    load_chunk(0, 0);

    {
        const __half2 sc = __floats2half2_rn(0.125f, 0.125f);
        for (int idx = tid; idx < 512; idx += 128) {
            int r = idx >> 3, c8 = (idx & 7) * 8;
            uint4 v = *(const uint4*)(Qg + (size_t)(b * NQ + r) * CQ + h * D_ + c8);
            __half2* s = (__half2*)&v;
            __half2* d = (__half2*)&Qs[r][c8];
            d[0] = __hmul2(s[0], sc); d[1] = __hmul2(s[1], sc);
            d[2] = __hmul2(s[2], sc); d[3] = __hmul2(s[3], sc);
        }
    }

    const int qa_row = lane & 15;
    const int qa_ko  = ((lane >> 4) & 1) * 8;
    const int kb_row = (lane & 7) + ((lane >> 4) & 1) * 8;
    const int kb_ko  = ((lane >> 3) & 1) * 8;
    const int vt_row = (lane & 7) + ((lane >> 3) & 1) * 8;
    const int vt_co  = ((lane >> 4) & 1) * 8;

    float m0 = -1e30f, m1 = -1e30f, l0 = 0.f, l1 = 0.f;
    float o[8][4];
    #pragma unroll
    for (int i = 0; i < 8; i++)
        #pragma unroll
        for (int j = 0; j < 4; j++) o[i][j] = 0.f;

    for (int c = 0; c < N_CHUNKS; c++) {
        const int cur = c & 1;
        if (c + 1 < N_CHUNKS) { load_chunk(c + 1, cur ^ 1); CP_WAIT(1); }
        else                  { CP_WAIT(0); }
        __syncthreads();

        float s[8][4];
        #pragma unroll
        for (int i = 0; i < 8; i++)
            #pragma unroll
            for (int j = 0; j < 4; j++) s[i][j] = 0.f;

        #pragma unroll
        for (int kk = 0; kk < 4; kk++) {
            uint32_t a0, a1, a2, a3;
            ldsm_x4(smem_u32(&Qs[w * 16 + qa_row][kk * 16 + qa_ko]), a0, a1, a2, a3);
            #pragma unroll
            for (int ng = 0; ng < 4; ng++) {
                uint32_t b0, b1, b2, b3;
                ldsm_x4(smem_u32(&Ks[cur][ng * 16 + kb_row][kk * 16 + kb_ko]),
                        b0, b1, b2, b3);
                mma_f16(s[2 * ng],     a0, a1, a2, a3, b0, b1);
                mma_f16(s[2 * ng + 1], a0, a1, a2, a3, b2, b3);
            }
        }

        float mx0 = -1e30f, mx1 = -1e30f;
        #pragma unroll
        for (int nt = 0; nt < 8; nt++) {
            mx0 = fmaxf(mx0, fmaxf(s[nt][0], s[nt][1]));
            mx1 = fmaxf(mx1, fmaxf(s[nt][2], s[nt][3]));
        }
        #pragma unroll
        for (int ofs = 1; ofs < 4; ofs <<= 1) {
            mx0 = fmaxf(mx0, __shfl_xor_sync(0xffffffffu, mx0, ofs));
            mx1 = fmaxf(mx1, __shfl_xor_sync(0xffffffffu, mx1, ofs));
        }
        float M0 = fmaxf(m0, mx0), M1 = fmaxf(m1, mx1);
        float c0 = __expf(m0 - M0), c1 = __expf(m1 - M1);
        float ls0 = 0.f, ls1 = 0.f;
        #pragma unroll
        for (int nt = 0; nt < 8; nt++) {
            s[nt][0] = __expf(s[nt][0] - M0); ls0 += s[nt][0];
            s[nt][1] = __expf(s[nt][1] - M0); ls0 += s[nt][1];
            s[nt][2] = __expf(s[nt][2] - M1); ls1 += s[nt][2];
            s[nt][3] = __expf(s[nt][3] - M1); ls1 += s[nt][3];
        }
        #pragma unroll
        for (int ofs = 1; ofs < 4; ofs <<= 1) {
            ls0 += __shfl_xor_sync(0xffffffffu, ls0, ofs);
            ls1 += __shfl_xor_sync(0xffffffffu, ls1, ofs);
        }
        l0 = l0 * c0 + ls0;  l1 = l1 * c1 + ls1;
        m0 = M0;  m1 = M1;
        #pragma unroll
        for (int nt = 0; nt < 8; nt++) {
            o[nt][0] *= c0; o[nt][1] *= c0;
            o[nt][2] *= c1; o[nt][3] *= c1;
        }

        uint32_t pu[8][2];
        #pragma unroll
        for (int nt = 0; nt < 8; nt++) {
            pu[nt][0] = pack_h2(s[nt][0], s[nt][1]);
            pu[nt][1] = pack_h2(s[nt][2], s[nt][3]);
        }

        #pragma unroll
        for (int t = 0; t < 4; t++) {
            uint32_t a0 = pu[2 * t][0],     a1 = pu[2 * t][1];
            uint32_t a2 = pu[2 * t + 1][0], a3 = pu[2 * t + 1][1];
            #pragma unroll
            for (int dg = 0; dg < 4; dg++) {
                uint32_t b0, b1, b2, b3;
                ldsm_x4_t(smem_u32(&Vs[cur][t * 16 + vt_row][dg * 16 + vt_co]),
                          b0, b1, b2, b3);
                mma_f16(o[2 * dg],     a0, a1, a2, a3, b0, b1);
                mma_f16(o[2 * dg + 1], a0, a1, a2, a3, b2, b3);
            }
        }
        __syncthreads();
    }

    float* accp = accP + (size_t)blockIdx.x * 64 * 64;
    const int r0 = w * 16 + (lane >> 2), r1 = r0 + 8;
    const int cb = (lane & 3) * 2;
    #pragma unroll
    for (int nt = 0; nt < 8; nt++) {
        st2(&accp[r0 * 64 + nt * 8 + cb], o[nt][0], o[nt][1]);
        st2(&accp[r1 * 64 + nt * 8 + cb], o[nt][2], o[nt][3]);
    }
    if ((lane & 3) == 0) {
        mP[(size_t)blockIdx.x * 64 + r0] = m0;
        lP[(size_t)blockIdx.x * 64 + r0] = l0;
        mP[(size_t)blockIdx.x * 64 + r1] = m1;
        lP[(size_t)blockIdx.x * 64 + r1] = l1;
    }
}

__global__ __launch_bounds__(256) void attention_combine(
    const float* __restrict__ accP, const float* __restrict__ mP,
    const float* __restrict__ lP, __half* __restrict__ Xg)
{
    __shared__ float sw[SPLIT][64];
    __shared__ float sden[64];
    const int bh = blockIdx.x;
    const int b = bh / H_, h = bh % H_;
    const int tid = threadIdx.x;

    if (tid < 64) {
        int r = tid;
        float M = -1e30f;
        #pragma unroll
        for (int s = 0; s < SPLIT; s++)
            M = fmaxf(M, mP[(size_t)(bh * SPLIT + s) * 64 + r]);
        float den = 0.f;
        #pragma unroll
        for (int s = 0; s < SPLIT; s++) {
            float w = __expf(mP[(size_t)(bh * SPLIT + s) * 64 + r] - M);
            sw[s][r] = w;
            den += w * lP[(size_t)(bh * SPLIT + s) * 64 + r];
        }
        sden[r] = den;
    }
    __syncthreads();

    for (int idx = tid; idx < 64 * 64; idx += 256) {
        int r = idx >> 6, d = idx & 63;
        float num = 0.f;
        #pragma unroll
        for (int s = 0; s < SPLIT; s++)
            num += sw[s][r] * accP[(size_t)(bh * SPLIT + s) * 4096 + idx];
        Xg[(size_t)(b * NQ + r) * CQ + h * D_ + d] = __float2half_rn(num / sden[r]);
    }
}

// ---------------------------------------------------------------------------
extern "C" void kernel_launch(void* const* d_in, const int* in_sizes, int n_in,
                              void* d_out, int out_size)
{
    const float* query = (const float*)d_in[0];
    const float* kv    = (const float*)d_in[1];
    const float* Wq    = (const float*)d_in[2];
    const float* bq    = (const float*)d_in[3];
    const float* Wk    = (const float*)d_in[4];
    const float* bk    = (const float*)d_in[5];
    const float* Wv    = (const float*)d_in[6];
    const float* bv    = (const float*)d_in[7];
    const float* Wo    = (const float*)d_in[8];
    const float* bo    = (const float*)d_in[9];
    float* out = (float*)d_out;

    float *accp, *mp, *lp;
    __half *qa, *qh, *xh, *kp, *vp, *kva, *wkvt, *wqth, *wqtl, *woth, *wotl;
    cudaGetSymbolAddress((void**)&qa, g_qa);
    cudaGetSymbolAddress((void**)&qh, g_qh);
    cudaGetSymbolAddress((void**)&xh, g_xh);
    cudaGetSymbolAddress((void**)&kp, g_kh);
    cudaGetSymbolAddress((void**)&vp, g_vh);
    cudaGetSymbolAddress((void**)&kva, g_kva);
    cudaGetSymbolAddress((void**)&wkvt, g_wkvt);
    cudaGetSymbolAddress((void**)&wqth, g_wqth);
    cudaGetSymbolAddress((void**)&wqtl, g_wqtl);
    cudaGetSymbolAddress((void**)&woth, g_woth);
    cudaGetSymbolAddress((void**)&wotl, g_wotl);
    cudaGetSymbolAddress((void**)&accp, g_accP);
    cudaGetSymbolAddress((void**)&mp, g_mP);
    cudaGetSymbolAddress((void**)&lp, g_lP);

    cudaFuncSetAttribute(hgemm_kv,
                         cudaFuncAttributeMaxDynamicSharedMemorySize, HGEMM_SMEM);

    // half-split element counts (ELEMENT units made explicit)
    const size_t M_HALF       = (size_t)B_ * NKV / 2;    // 32768 rows
    const size_t ELEMS_HALF   = M_HALF * CKV;            // elements in half of kv/kva
    const size_t C_HALF       = M_HALF * CQ;             // elements in half of K/V out
    const size_t N4_HALF      = ELEMS_HALF / 4;          // float4 count per half

    // side stream (high priority so round1 CTAs slot into GEMM0 wave gaps)
    int prLo, prHi;
    cudaDeviceGetStreamPriorityRange(&prLo, &prHi);
    cudaStream_t s2;
    cudaStreamCreateWithPriority(&s2, cudaStreamNonBlocking, prHi);
    cudaEvent_t eFork, eW, eR1, eJoin;
    cudaEventCreateWithFlags(&eFork, cudaEventDisableTiming);
    cudaEventCreateWithFlags(&eW, cudaEventDisableTiming);
    cudaEventCreateWithFlags(&eR1, cudaEventDisableTiming);
    cudaEventCreateWithFlags(&eJoin, cudaEventDisableTiming);

    cudaEventRecord(eFork, 0);
    cudaStreamWaitEvent(s2, eFork, 0);

    // main: round first half of kv
    round_kernel<<<2048, 256>>>(kv, kva, N4_HALF);

    // side: weight transposes (GEMM dep) -> round second half -> q path
    transpose_f16_tiled<<<dim3(CKV / 32, CQ / 32), 256, 0, s2>>>(Wk, wkvt);
    transpose_f16_tiled<<<dim3(CKV / 32, CQ / 32), 256, 0, s2>>>(Wv, wkvt + (size_t)CQ * CKV);
    cudaEventRecord(eW, s2);
    round_kernel<<<2048, 256, 0, s2>>>(kv + ELEMS_HALF, kva + ELEMS_HALF, N4_HALF);
    cudaEventRecord(eR1, s2);
    round_kernel<<<384, 256, 0, s2>>>(query, qa, (size_t)B_ * NQ * CQ / 4);
    transpose_split768_tiled<<<dim3(CQ / 32, CQ / 32), 256, 0, s2>>>(Wq, wqth, wqtl);
    transpose_split768_tiled<<<dim3(CQ / 32, CQ / 32), 256, 0, s2>>>(Wo, woth, wotl);
    hgemm_qo<__half><<<dim3(CQ / 64, (B_ * NQ) / 64), 128, 0, s2>>>(qa, wqth, wqtl, bq, qh);
    cudaEventRecord(eJoin, s2);

    // main: fused K+V projection in two m-halves
    cudaStreamWaitEvent(0, eW, 0);
    hgemm_kv<<<dim3(2 * CQ / 128, (unsigned)(M_HALF / 128)), 256, HGEMM_SMEM>>>(
        kva, wkvt, bk, bv, kp, vp);
    cudaStreamWaitEvent(0, eR1, 0);
    hgemm_kv<<<dim3(2 * CQ / 128, (unsigned)(M_HALF / 128)), 256, HGEMM_SMEM>>>(
        kva + ELEMS_HALF, wkvt, bk, bv, kp + C_HALF, vp + C_HALF);

    // join q path, then attention + combine + output projection
    cudaStreamWaitEvent(0, eJoin, 0);
    attention_hmma<<<B_ * H_ * SPLIT, 128>>>(qh, kp, vp, accp, mp, lp);
    attention_combine<<<B_ * H_, 256>>>(accp, mp, lp, xh);
    hgemm_qo<float><<<dim3(CQ / 64, (B_ * NQ) / 64), 128>>>(xh, woth, wotl, bo, out);

    cudaEventDestroy(eFork);
    cudaEventDestroy(eW);
    cudaEventDestroy(eR1);
    cudaEventDestroy(eJoin);
    cudaStreamDestroy(s2);
}

// round 17
// speedup vs baseline: 1.0313x; 1.0228x over previous
#include <cuda_runtime.h>
#include <cuda_bf16.h>
#include <cuda_fp16.h>
#include <math.h>
#include <stdint.h>

#define B_   16
#define NQ   64
#define NKV  4096
#define CQ   768
#define CKV  1024
#define H_   12
#define D_   64
#define SPLIT 8

// ---------------- scratch (device globals; allocation-free) ----------------
__device__ __half g_qa  [(size_t)B_ * NQ * CQ];
__device__ __half g_qh  [(size_t)B_ * NQ * CQ];
__device__ __half g_xh  [(size_t)B_ * NQ * CQ];
__device__ __half g_kh  [(size_t)B_ * NKV * CQ];
__device__ __half g_vh  [(size_t)B_ * NKV * CQ];
__device__ __half g_kva [(size_t)B_ * NKV * CKV];
__device__ __half g_wkvt[(size_t)2 * CQ * CKV];
__device__ __half g_wqth[(size_t)CQ * CQ];
__device__ __half g_wqtl[(size_t)CQ * CQ];
__device__ __half g_woth[(size_t)CQ * CQ];
__device__ __half g_wotl[(size_t)CQ * CQ];
__device__ float g_accP[(size_t)B_ * H_ * SPLIT * NQ * D_];
__device__ float g_mP[(size_t)B_ * H_ * SPLIT * NQ];
__device__ float g_lP[(size_t)B_ * H_ * SPLIT * NQ];

// ---------------- helpers ----------------
__device__ __forceinline__ uint32_t smem_u32(const void* p) {
    uint32_t a;
    asm("{ .reg .u64 t; cvta.to.shared.u64 t, %1; cvt.u32.u64 %0, t; }"
        : "=r"(a) : "l"(p));
    return a;
}
__device__ __forceinline__ void cp16(uint32_t s, const void* g) {
    asm volatile("cp.async.cg.shared.global [%0], [%1], 16;\n"
                 :: "r"(s), "l"(__cvta_generic_to_global(g)) : "memory");
}
#define CP_COMMIT() asm volatile("cp.async.commit_group;\n" ::: "memory")
#define CP_WAIT(n)  asm volatile("cp.async.wait_group %0;\n" :: "n"(n) : "memory")

__device__ __forceinline__ void ldsm_x4(uint32_t addr, uint32_t& r0, uint32_t& r1,
                                        uint32_t& r2, uint32_t& r3) {
    asm volatile("ldmatrix.sync.aligned.m8n8.x4.shared.b16 {%0,%1,%2,%3}, [%4];"
                 : "=r"(r0), "=r"(r1), "=r"(r2), "=r"(r3) : "r"(addr));
}
__device__ __forceinline__ void ldsm_x4_t(uint32_t addr, uint32_t& r0, uint32_t& r1,
                                          uint32_t& r2, uint32_t& r3) {
    asm volatile("ldmatrix.sync.aligned.m8n8.x4.trans.shared.b16 {%0,%1,%2,%3}, [%4];"
                 : "=r"(r0), "=r"(r1), "=r"(r2), "=r"(r3) : "r"(addr));
}
__device__ __forceinline__ void mma_f16(float* d, uint32_t a0, uint32_t a1,
                                        uint32_t a2, uint32_t a3,
                                        uint32_t b0, uint32_t b1) {
    asm volatile(
        "mma.sync.aligned.m16n8k16.row.col.f32.f16.f16.f32 "
        "{%0,%1,%2,%3}, {%4,%5,%6,%7}, {%8,%9}, {%0,%1,%2,%3};"
        : "+f"(d[0]), "+f"(d[1]), "+f"(d[2]), "+f"(d[3])
        : "r"(a0), "r"(a1), "r"(a2), "r"(a3), "r"(b0), "r"(b1));
}
__device__ __forceinline__ uint32_t pack_h2(float a, float b) {
    __half2 h = __floats2half2_rn(a, b);
    return *(uint32_t*)&h;
}
__device__ __forceinline__ void st2(float* p, float a, float b) {
    float2 v = { a, b }; *(float2*)p = v;
}
__device__ __forceinline__ void st2(__half* p, float a, float b) {
    *(uint32_t*)p = pack_h2(a, b);
}

// ---------------------------------------------------------------------------
// prep kernels
// ---------------------------------------------------------------------------
__global__ __launch_bounds__(256) void round_kernel(
    const float* __restrict__ src, __half* __restrict__ dst, size_t n4)
{
    size_t i = ((size_t)blockIdx.x * blockDim.x + threadIdx.x) * 2;
    size_t stride = (size_t)gridDim.x * blockDim.x * 2;
    for (; i < n4; i += stride) {
        float4 x = ((const float4*)src)[i];
        float4 y = ((const float4*)src)[i + 1];
        ((__half2*)dst)[i * 2]     = __floats2half2_rn(x.x, x.y);
        ((__half2*)dst)[i * 2 + 1] = __floats2half2_rn(x.z, x.w);
        ((__half2*)dst)[i * 2 + 2] = __floats2half2_rn(y.x, y.y);
        ((__half2*)dst)[i * 2 + 3] = __floats2half2_rn(y.z, y.w);
    }
}

__global__ __launch_bounds__(256) void transpose_f16_tiled(
    const float* __restrict__ W, __half* __restrict__ th)
{
    __shared__ float t[32][33];
    const int kb = blockIdx.x * 32, nb = blockIdx.y * 32;
    const int tx = threadIdx.x & 31, ty = threadIdx.x >> 5;
    #pragma unroll
    for (int i = ty; i < 32; i += 8)
        t[i][tx] = W[(size_t)(kb + i) * CQ + nb + tx];
    __syncthreads();
    #pragma unroll
    for (int i = ty; i < 32; i += 8)
        th[(size_t)(nb + i) * CKV + kb + tx] = __float2half_rn(t[tx][i]);
}

__global__ __launch_bounds__(256) void transpose_split768_tiled(
    const float* __restrict__ W, __half* __restrict__ th, __half* __restrict__ tl)
{
    __shared__ float t[32][33];
    const int kb = blockIdx.x * 32, nb = blockIdx.y * 32;
    const int tx = threadIdx.x & 31, ty = threadIdx.x >> 5;
    #pragma unroll
    for (int i = ty; i < 32; i += 8)
        t[i][tx] = W[(size_t)(kb + i) * CQ + nb + tx];
    __syncthreads();
    #pragma unroll
    for (int i = ty; i < 32; i += 8) {
        float x = t[tx][i];
        __half h = __float2half_rn(x);
        th[(size_t)(nb + i) * CQ + kb + tx] = h;
        tl[(size_t)(nb + i) * CQ + kb + tx] = __float2half_rn(x - __half2float(h));
    }
}

// ---------------------------------------------------------------------------
// Fused K+V HMMA fp16 GEMM, k-chunk 64 (CTA 128x128x64, 8 warps, occ 2)
// ---------------------------------------------------------------------------
#define GR_STRIDE 144
#define TILE_B (128 * GR_STRIDE)
#define STAGE_B (2 * TILE_B)
#define STAGES 3
#define HGEMM_SMEM (STAGES * STAGE_B)
#define KT_N (CKV / 64)

__global__ __launch_bounds__(256, 2) void hgemm_kv(
    const __half* __restrict__ A_g, const __half* __restrict__ Bkv,
    const float* __restrict__ bk, const float* __restrict__ bv,
    __half* __restrict__ Kout, __half* __restrict__ Vout)
{
    extern __shared__ char smem[];
    const uint32_t sbase = smem_u32(smem);
    const int tid = threadIdx.x;
    const int wid = tid >> 5, lane = tid & 31;
    const int wm = (wid & 1) * 64;
    const int wn = (wid >> 1) * 32;
    const int m0 = blockIdx.y * 128, n0 = blockIdx.x * 128;

    const int l_row = tid >> 3;
    const int l_c16 = tid & 7;
    const uint32_t l_soff = (uint32_t)(l_row * GR_STRIDE + l_c16 * 16);

    const int a_row = lane & 15;
    const int a_ko  = ((lane >> 4) & 1) * 8;
    const int b_row = (lane & 7) + ((lane >> 4) & 1) * 8;
    const int b_ko  = ((lane >> 3) & 1) * 8;

    float acc[4][4][4];
    #pragma unroll
    for (int i = 0; i < 4; i++)
        #pragma unroll
        for (int j = 0; j < 4; j++)
            #pragma unroll
            for (int c = 0; c < 4; c++) acc[i][j][c] = 0.f;

    auto load_stage = [&](int kt, int s) {
        const uint32_t sb = sbase + s * STAGE_B;
        const int ke = kt * 64;
        #pragma unroll
        for (int j = 0; j < 4; j++) {
            const int row = l_row + j * 32;
            const uint32_t so = l_soff + (uint32_t)(j * 32 * GR_STRIDE);
            cp16(sb + so,          A_g + (size_t)(m0 + row) * CKV + ke + l_c16 * 8);
            cp16(sb + TILE_B + so, Bkv + (size_t)(n0 + row) * CKV + ke + l_c16 * 8);
        }
        CP_COMMIT();
    };

    load_stage(0, 0);
    load_stage(1, 1);

    for (int kt = 0; kt < KT_N; kt++) {
        CP_WAIT(1);
        __syncthreads();

        const int nkt = kt + STAGES - 1;
        if (nkt < KT_N) load_stage(nkt, nkt % STAGES);
        else CP_COMMIT();

        const uint32_t sb = sbase + (kt % STAGES) * STAGE_B;
        #pragma unroll
        for (int kb = 0; kb < 64; kb += 16) {
            uint32_t ah[4][4];
            #pragma unroll
            for (int mt = 0; mt < 4; mt++) {
                uint32_t ra = sb + (uint32_t)((wm + mt * 16 + a_row) * GR_STRIDE
                                              + (a_ko + kb) * 2);
                ldsm_x4(ra, ah[mt][0], ah[mt][1], ah[mt][2], ah[mt][3]);
            }
            uint32_t bh[4][2];
            #pragma unroll
            for (int np = 0; np < 2; np++) {
                uint32_t rb = sb + TILE_B +
                              (uint32_t)((wn + np * 16 + b_row) * GR_STRIDE
                                         + (b_ko + kb) * 2);
                ldsm_x4(rb, bh[np * 2][0], bh[np * 2][1], bh[np * 2 + 1][0], bh[np * 2 + 1][1]);
            }
            #pragma unroll
            for (int mt = 0; mt < 4; mt++)
                #pragma unroll
                for (int nt = 0; nt < 4; nt++)
                    mma_f16(acc[mt][nt], ah[mt][0], ah[mt][1], ah[mt][2], ah[mt][3],
                            bh[nt][0], bh[nt][1]);
        }
    }

    const bool isV = (n0 >= CQ);
    const float* bias = isV ? bv : bk;
    __half* C = isV ? Vout : Kout;
    const int nc0 = isV ? (n0 - CQ) : n0;

    const int er = lane >> 2, ec = (lane & 3) * 2;
    #pragma unroll
    for (int mt = 0; mt < 4; mt++) {
        #pragma unroll
        for (int nt = 0; nt < 4; nt++) {
            const int col = nc0 + wn + nt * 8 + ec;
            const float b0 = bias[col], b1 = bias[col + 1];
            __half* p0 = C + (size_t)(m0 + wm + mt * 16 + er) * CQ + col;
            __half* p1 = p0 + 8 * CQ;
            st2(p0, acc[mt][nt][0] + b0, acc[mt][nt][1] + b1);
            st2(p1, acc[mt][nt][2] + b0, acc[mt][nt][3] + b1);
        }
    }
}

// ---------------------------------------------------------------------------
// Small HMMA fp16x2 GEMM (Q / O projections)
// ---------------------------------------------------------------------------
#define QO_TILE_B 5120
#define QO_STAGE_B (3 * QO_TILE_B)
#define QO_STAGES 3
#define QO_KT (CQ / 32)

template <typename OutT>
__global__ __launch_bounds__(128) void hgemm_qo(
    const __half* __restrict__ A_g, const __half* __restrict__ Bh_g,
    const __half* __restrict__ Bl_g, const float* __restrict__ bias,
    OutT* __restrict__ C)
{
    __shared__ char smem[QO_STAGES * QO_STAGE_B];
    const uint32_t sbase = smem_u32(smem);
    const int tid = threadIdx.x;
    const int wid = tid >> 5, lane = tid & 31;
    const int wm = (wid & 1) * 32;
    const int wn = (wid >> 1) * 32;
    const int m0 = blockIdx.y * 64, n0 = blockIdx.x * 64;

    const int lr = tid >> 1;
    const int lc = (tid & 1) * 16;
    const uint32_t s_off = (uint32_t)(lr * 80 + (tid & 1) * 32);

    const __half* gA  = A_g  + (size_t)(m0 + lr) * CQ + lc;
    const __half* gBh = Bh_g + (size_t)(n0 + lr) * CQ + lc;
    const __half* gBl = Bl_g + (size_t)(n0 + lr) * CQ + lc;

    const int a_row = lane & 15;
    const int a_ko  = ((lane >> 4) & 1) * 8;
    const int b_row = (lane & 7) + ((lane >> 4) & 1) * 8;
    const int b_ko  = ((lane >> 3) & 1) * 8;

    float acc[2][4][4];
    #pragma unroll
    for (int i = 0; i < 2; i++)
        #pragma unroll
        for (int j = 0; j < 4; j++)
            #pragma unroll
            for (int c = 0; c < 4; c++) acc[i][j][c] = 0.f;

    auto load_stage = [&](int kt, int s) {
        const uint32_t sb = sbase + s * QO_STAGE_B;
        const int ke = kt * 32;
        cp16(sb + s_off,                    gA  + ke);
        cp16(sb + s_off + 16,               gA  + ke + 8);
        cp16(sb + QO_TILE_B + s_off,        gBh + ke);
        cp16(sb + QO_TILE_B + s_off + 16,   gBh + ke + 8);
        cp16(sb + 2*QO_TILE_B + s_off,      gBl + ke);
        cp16(sb + 2*QO_TILE_B + s_off + 16, gBl + ke + 8);
    };

    load_stage(0, 0); CP_COMMIT();
    load_stage(1, 1); CP_COMMIT();

    for (int kt = 0; kt < QO_KT; kt++) {
        CP_WAIT(1);
        __syncthreads();

        const int nkt = kt + QO_STAGES - 1;
        if (nkt < QO_KT) load_stage(nkt, nkt % QO_STAGES);
        CP_COMMIT();

        const uint32_t sb = sbase + (kt % QO_STAGES) * QO_STAGE_B;
        #pragma unroll
        for (int kb = 0; kb < 32; kb += 16) {
            uint32_t a[2][4];
            #pragma unroll
            for (int mt = 0; mt < 2; mt++) {
                uint32_t ra = sb + (uint32_t)((wm + mt * 16 + a_row) * 80 + (a_ko + kb) * 2);
                ldsm_x4(ra, a[mt][0], a[mt][1], a[mt][2], a[mt][3]);
            }
            uint32_t bh[4][2], bl[4][2];
            #pragma unroll
            for (int ng = 0; ng < 2; ng++) {
                uint32_t rbh = sb + QO_TILE_B +
                               (uint32_t)((wn + ng * 16 + b_row) * 80 + (b_ko + kb) * 2);
                ldsm_x4(rbh, bh[2*ng][0], bh[2*ng][1], bh[2*ng+1][0], bh[2*ng+1][1]);
                ldsm_x4(rbh + QO_TILE_B, bl[2*ng][0], bl[2*ng][1], bl[2*ng+1][0], bl[2*ng+1][1]);
            }
            #pragma unroll
            for (int mt = 0; mt < 2; mt++)
                #pragma unroll
                for (int nt = 0; nt < 4; nt++) {
                    mma_f16(acc[mt][nt], a[mt][0], a[mt][1], a[mt][2], a[mt][3],
                            bh[nt][0], bh[nt][1]);
                    mma_f16(acc[mt][nt], a[mt][0], a[mt][1], a[mt][2], a[mt][3],
                            bl[nt][0], bl[nt][1]);
                }
        }
    }

    const int er = lane >> 2, ec = (lane & 3) * 2;
    #pragma unroll
    for (int mt = 0; mt < 2; mt++) {
        #pragma unroll
        for (int nt = 0; nt < 4; nt++) {
            const int col = n0 + wn + nt * 8 + ec;
            const float b0 = bias[col], b1 = bias[col + 1];
            OutT* p0 = C + (size_t)(m0 + wm + mt * 16 + er) * CQ + col;
            OutT* p1 = p0 + 8 * CQ;
            st2(p0, acc[mt][nt][0] + b0, acc[mt][nt][1] + b1);
            st2(p1, acc[mt][nt][2] + b0, acc[mt][nt][3] + b1);
        }
    }
}

// ---------------------------------------------------------------------------
// HMMA split-KV flash attention partial (batch-sliced via bh_base)
// ---------------------------------------------------------------------------
#define KV_PER_SPLIT (NKV / SPLIT)
#define N_CHUNKS (KV_PER_SPLIT / 64)

__global__ __launch_bounds__(128) void attention_hmma(
    const __half* __restrict__ Qg, const __half* __restrict__ Kg,
    const __half* __restrict__ Vg,
    float* __restrict__ accP, float* __restrict__ mP, float* __restrict__ lP,
    int bh_base)
{
    __shared__ __half Qs[64][72];
    __shared__ __half Ks[2][64][72];
    __shared__ __half Vs[2][64][72];

    const int gidx = bh_base * SPLIT + blockIdx.x;
    const int bh = gidx / SPLIT;
    const int sp = gidx % SPLIT;
    const int b = bh / H_, h = bh % H_;
    const int tid = threadIdx.x;
    const int w = tid >> 5, lane = tid & 31;
    const int kv_lo = sp * KV_PER_SPLIT;

    auto load_chunk = [&](int c, int buf) {
        const int kv0 = kv_lo + c * 64;
        #pragma unroll
        for (int idx = tid; idx < 512; idx += 128) {
            int r = idx >> 3, sg = idx & 7;
            size_t gofs = (size_t)(b * NKV + kv0 + r) * CQ + h * D_ + sg * 8;
            cp16(smem_u32(&Ks[buf][r][sg * 8]), Kg + gofs);
            cp16(smem_u32(&Vs[buf][r][sg * 8]), Vg + gofs);
        }
        CP_COMMIT();
    };

    load_chunk(0, 0);

    {
        const __half2 sc = __floats2half2_rn(0.125f, 0.125f);
        for (int idx = tid; idx < 512; idx += 128) {
            int r = idx >> 3, c8 = (idx & 7) * 8;
            uint4 v = *(const uint4*)(Qg + (size_t)(b * NQ + r) * CQ + h * D_ + c8);
            __half2* s = (__half2*)&v;
            __half2* d = (__half2*)&Qs[r][c8];
            d[0] = __hmul2(s[0], sc); d[1] = __hmul2(s[1], sc);
            d[2] = __hmul2(s[2], sc); d[3] = __hmul2(s[3], sc);
        }
    }

    const int qa_row = lane & 15;
    const int qa_ko  = ((lane >> 4) & 1) * 8;
    const int kb_row = (lane & 7) + ((lane >> 4) & 1) * 8;
    const int kb_ko  = ((lane >> 3) & 1) * 8;
    const int vt_row = (lane & 7) + ((lane >> 3) & 1) * 8;
    const int vt_co  = ((lane >> 4) & 1) * 8;

    float m0 = -1e30f, m1 = -1e30f, l0 = 0.f, l1 = 0.f;
    float o[8][4];
    #pragma unroll
    for (int i = 0; i < 8; i++)
        #pragma unroll
        for (int j = 0; j < 4; j++) o[i][j] = 0.f;

    for (int c = 0; c < N_CHUNKS; c++) {
        const int cur = c & 1;
        if (c + 1 < N_CHUNKS) { load_chunk(c + 1, cur ^ 1); CP_WAIT(1); }
        else                  { CP_WAIT(0); }
        __syncthreads();

        float s[8][4];
        #pragma unroll
        for (int i = 0; i < 8; i++)
            #pragma unroll
            for (int j = 0; j < 4; j++) s[i][j] = 0.f;

        #pragma unroll
        for (int kk = 0; kk < 4; kk++) {
            uint32_t a0, a1, a2, a3;
            ldsm_x4(smem_u32(&Qs[w * 16 + qa_row][kk * 16 + qa_ko]), a0, a1, a2, a3);
            #pragma unroll
            for (int ng = 0; ng < 4; ng++) {
                uint32_t b0, b1, b2, b3;
                ldsm_x4(smem_u32(&Ks[cur][ng * 16 + kb_row][kk * 16 + kb_ko]),
                        b0, b1, b2, b3);
                mma_f16(s[2 * ng],     a0, a1, a2, a3, b0, b1);
                mma_f16(s[2 * ng + 1], a0, a1, a2, a3, b2, b3);
            }
        }

        float mx0 = -1e30f, mx1 = -1e30f;
        #pragma unroll
        for (int nt = 0; nt < 8; nt++) {
            mx0 = fmaxf(mx0, fmaxf(s[nt][0], s[nt][1]));
            mx1 = fmaxf(mx1, fmaxf(s[nt][2], s[nt][3]));
        }
        #pragma unroll
        for (int ofs = 1; ofs < 4; ofs <<= 1) {
            mx0 = fmaxf(mx0, __shfl_xor_sync(0xffffffffu, mx0, ofs));
            mx1 = fmaxf(mx1, __shfl_xor_sync(0xffffffffu, mx1, ofs));
        }
        float M0 = fmaxf(m0, mx0), M1 = fmaxf(m1, mx1);
        float c0 = __expf(m0 - M0), c1 = __expf(m1 - M1);
        float ls0 = 0.f, ls1 = 0.f;
        #pragma unroll
        for (int nt = 0; nt < 8; nt++) {
            s[nt][0] = __expf(s[nt][0] - M0); ls0 += s[nt][0];
            s[nt][1] = __expf(s[nt][1] - M0); ls0 += s[nt][1];
            s[nt][2] = __expf(s[nt][2] - M1); ls1 += s[nt][2];
            s[nt][3] = __expf(s[nt][3] - M1); ls1 += s[nt][3];
        }
        #pragma unroll
        for (int ofs = 1; ofs < 4; ofs <<= 1) {
            ls0 += __shfl_xor_sync(0xffffffffu, ls0, ofs);
            ls1 += __shfl_xor_sync(0xffffffffu, ls1, ofs);
        }
        l0 = l0 * c0 + ls0;  l1 = l1 * c1 + ls1;
        m0 = M0;  m1 = M1;
        #pragma unroll
        for (int nt = 0; nt < 8; nt++) {
            o[nt][0] *= c0; o[nt][1] *= c0;
            o[nt][2] *= c1; o[nt][3] *= c1;
        }

        uint32_t pu[8][2];
        #pragma unroll
        for (int nt = 0; nt < 8; nt++) {
            pu[nt][0] = pack_h2(s[nt][0], s[nt][1]);
            pu[nt][1] = pack_h2(s[nt][2], s[nt][3]);
        }

        #pragma unroll
        for (int t = 0; t < 4; t++) {
            uint32_t a0 = pu[2 * t][0],     a1 = pu[2 * t][1];
            uint32_t a2 = pu[2 * t + 1][0], a3 = pu[2 * t + 1][1];
            #pragma unroll
            for (int dg = 0; dg < 4; dg++) {
                uint32_t b0, b1, b2, b3;
                ldsm_x4_t(smem_u32(&Vs[cur][t * 16 + vt_row][dg * 16 + vt_co]),
                          b0, b1, b2, b3);
                mma_f16(o[2 * dg],     a0, a1, a2, a3, b0, b1);
                mma_f16(o[2 * dg + 1], a0, a1, a2, a3, b2, b3);
            }
        }
        __syncthreads();
    }

    float* accp = accP + (size_t)gidx * 64 * 64;
    const int r0 = w * 16 + (lane >> 2), r1 = r0 + 8;
    const int cb = (lane & 3) * 2;
    #pragma unroll
    for (int nt = 0; nt < 8; nt++) {
        st2(&accp[r0 * 64 + nt * 8 + cb], o[nt][0], o[nt][1]);
        st2(&accp[r1 * 64 + nt * 8 + cb], o[nt][2], o[nt][3]);
    }
    if ((lane & 3) == 0) {
        mP[(size_t)gidx * 64 + r0] = m0;
        lP[(size_t)gidx * 64 + r0] = l0;
        mP[(size_t)gidx * 64 + r1] = m1;
        lP[(size_t)gidx * 64 + r1] = l1;
    }
}

__global__ __launch_bounds__(256) void attention_combine(
    const float* __restrict__ accP, const float* __restrict__ mP,
    const float* __restrict__ lP, __half* __restrict__ Xg)
{
    __shared__ float sw[SPLIT][64];
    __shared__ float sden[64];
    const int bh = blockIdx.x;
    const int b = bh / H_, h = bh % H_;
    const int tid = threadIdx.x;

    if (tid < 64) {
        int r = tid;
        float M = -1e30f;
        #pragma unroll
        for (int s = 0; s < SPLIT; s++)
            M = fmaxf(M, mP[(size_t)(bh * SPLIT + s) * 64 + r]);
        float den = 0.f;
        #pragma unroll
        for (int s = 0; s < SPLIT; s++) {
            float w = __expf(mP[(size_t)(bh * SPLIT + s) * 64 + r] - M);
            sw[s][r] = w;
            den += w * lP[(size_t)(bh * SPLIT + s) * 64 + r];
        }
        sden[r] = den;
    }
    __syncthreads();

    for (int idx = tid; idx < 64 * 64; idx += 256) {
        int r = idx >> 6, d = idx & 63;
        float num = 0.f;
        #pragma unroll
        for (int s = 0; s < SPLIT; s++)
            num += sw[s][r] * accP[(size_t)(bh * SPLIT + s) * 4096 + idx];
        Xg[(size_t)(b * NQ + r) * CQ + h * D_ + d] = __float2half_rn(num / sden[r]);
    }
}

// ---------------------------------------------------------------------------
extern "C" void kernel_launch(void* const* d_in, const int* in_sizes, int n_in,
                              void* d_out, int out_size)
{
    const float* query = (const float*)d_in[0];
    const float* kv    = (const float*)d_in[1];
    const float* Wq    = (const float*)d_in[2];
    const float* bq    = (const float*)d_in[3];
    const float* Wk    = (const float*)d_in[4];
    const float* bk    = (const float*)d_in[5];
    const float* Wv    = (const float*)d_in[6];
    const float* bv    = (const float*)d_in[7];
    const float* Wo    = (const float*)d_in[8];
    const float* bo    = (const float*)d_in[9];
    float* out = (float*)d_out;

    float *accp, *mp, *lp;
    __half *qa, *qh, *xh, *kp, *vp, *kva, *wkvt, *wqth, *wqtl, *woth, *wotl;
    cudaGetSymbolAddress((void**)&qa, g_qa);
    cudaGetSymbolAddress((void**)&qh, g_qh);
    cudaGetSymbolAddress((void**)&xh, g_xh);
    cudaGetSymbolAddress((void**)&kp, g_kh);
    cudaGetSymbolAddress((void**)&vp, g_vh);
    cudaGetSymbolAddress((void**)&kva, g_kva);
    cudaGetSymbolAddress((void**)&wkvt, g_wkvt);
    cudaGetSymbolAddress((void**)&wqth, g_wqth);
    cudaGetSymbolAddress((void**)&wqtl, g_wqtl);
    cudaGetSymbolAddress((void**)&woth, g_woth);
    cudaGetSymbolAddress((void**)&wotl, g_wotl);
    cudaGetSymbolAddress((void**)&accp, g_accP);
    cudaGetSymbolAddress((void**)&mp, g_mP);
    cudaGetSymbolAddress((void**)&lp, g_lP);

    cudaFuncSetAttribute(hgemm_kv,
                         cudaFuncAttributeMaxDynamicSharedMemorySize, HGEMM_SMEM);

    const size_t M_HALF     = (size_t)B_ * NKV / 2;    // 32768 rows = batches 0..7
    const size_t ELEMS_HALF = M_HALF * CKV;
    const size_t C_HALF     = M_HALF * CQ;
    const size_t N4_HALF    = ELEMS_HALF / 4;
    const int    BH_HALF    = (B_ / 2) * H_;           // 96

    int prLo, prHi;
    cudaDeviceGetStreamPriorityRange(&prLo, &prHi);
    cudaStream_t s2;
    cudaStreamCreateWithPriority(&s2, cudaStreamNonBlocking, prHi);
    cudaEvent_t eFork, eW, eR1, eG0, eA0;
    cudaEventCreateWithFlags(&eFork, cudaEventDisableTiming);
    cudaEventCreateWithFlags(&eW, cudaEventDisableTiming);
    cudaEventCreateWithFlags(&eR1, cudaEventDisableTiming);
    cudaEventCreateWithFlags(&eG0, cudaEventDisableTiming);
    cudaEventCreateWithFlags(&eA0, cudaEventDisableTiming);

    cudaEventRecord(eFork, 0);
    cudaStreamWaitEvent(s2, eFork, 0);

    // main: round first half of kv (batches 0..7)
    round_kernel<<<2048, 256>>>(kv, kva, N4_HALF);

    // side: weight transposes -> round second half -> q path
    transpose_f16_tiled<<<dim3(CKV / 32, CQ / 32), 256, 0, s2>>>(Wk, wkvt);
    transpose_f16_tiled<<<dim3(CKV / 32, CQ / 32), 256, 0, s2>>>(Wv, wkvt + (size_t)CQ * CKV);
    cudaEventRecord(eW, s2);
    round_kernel<<<2048, 256, 0, s2>>>(kv + ELEMS_HALF, kva + ELEMS_HALF, N4_HALF);
    cudaEventRecord(eR1, s2);
    round_kernel<<<384, 256, 0, s2>>>(query, qa, (size_t)B_ * NQ * CQ / 4);
    transpose_split768_tiled<<<dim3(CQ / 32, CQ / 32), 256, 0, s2>>>(Wq, wqth, wqtl);
    transpose_split768_tiled<<<dim3(CQ / 32, CQ / 32), 256, 0, s2>>>(Wo, woth, wotl);
    hgemm_qo<__half><<<dim3(CQ / 64, (B_ * NQ) / 64), 128, 0, s2>>>(qa, wqth, wqtl, bq, qh);

    // main: GEMM half 0 (batches 0..7)
    cudaStreamWaitEvent(0, eW, 0);
    hgemm_kv<<<dim3(2 * CQ / 128, (unsigned)(M_HALF / 128)), 256, HGEMM_SMEM>>>(
        kva, wkvt, bk, bv, kp, vp);
    cudaEventRecord(eG0, 0);

    // main: GEMM half 1 (batches 8..15)
    cudaStreamWaitEvent(0, eR1, 0);
    hgemm_kv<<<dim3(2 * CQ / 128, (unsigned)(M_HALF / 128)), 256, HGEMM_SMEM>>>(
        kva + ELEMS_HALF, wkvt, bk, bv, kp + C_HALF, vp + C_HALF);

    // side (high priority): attention for batches 0..7, overlapping GEMM h1
    // (qh ready: in-order on s2 after hgemm_qo)
    cudaStreamWaitEvent(s2, eG0, 0);
    attention_hmma<<<BH_HALF * SPLIT, 128, 0, s2>>>(qh, kp, vp, accp, mp, lp, 0);
    cudaEventRecord(eA0, s2);

    // main: attention for batches 8..15, then combine + O projection
    attention_hmma<<<BH_HALF * SPLIT, 128>>>(qh, kp, vp, accp, mp, lp, BH_HALF);
    cudaStreamWaitEvent(0, eA0, 0);
    attention_combine<<<B_ * H_, 256>>>(accp, mp, lp, xh);
    hgemm_qo<float><<<dim3(CQ / 64, (B_ * NQ) / 64), 128>>>(xh, woth, wotl, bo, out);

    cudaEventDestroy(eFork);
    cudaEventDestroy(eW);
    cudaEventDestroy(eR1);
    cudaEventDestroy(eG0);
    cudaEventDestroy(eA0);
    cudaStreamDestroy(s2);
}